// round 7
// baseline (speedup 1.0000x reference)
#include <cuda_runtime.h>
#include <cuda_bf16.h>
#include <cstdint>

// Problem constants
#define B_DIM   256
#define D_DIM   256
#define N_DIM   131072
#define TEMP_INV 20.0f
#define LOG2E   1.4426950408889634f
#define EPS_SM  1e-6f
#define EPS_LOG 1e-6f

#define NTILE   64                  // N columns per CTA tile
#define NTILES  (N_DIM / NTILE)     // 2048
#define LDA     264                 // 256 + 8 pad (bf16 elems)
#define LDB     264
#define GSTRIDE 160                 // per-row stride in g_partial (>= max grid)

// Named barriers: ready[b] = 1+b (producer->consumer), done[b] = 3+b (consumer->producer)
#define BAR_ARRIVE(id) asm volatile("bar.arrive %0, %1;" :: "r"(id), "r"(512) : "memory")
#define BAR_SYNC(id)   asm volatile("bar.sync %0, %1;"   :: "r"(id), "r"(512) : "memory")
#define BAR_SYNC_C(id) asm volatile("bar.sync %0, %1;"   :: "r"(id), "r"(256) : "memory")

// Device scratch
__device__ __align__(16) __nv_bfloat16 g_A[B_DIM * D_DIM];  // inputs * TEMP_INV * LOG2E
__device__ __align__(16) float g_partial[B_DIM * GSTRIDE];  // [m][g]
__device__ float g_tdot[B_DIM];
__device__ int g_done = 0;

// ---------------- helpers ----------------
__device__ __forceinline__ void ldm4(uint32_t &r0, uint32_t &r1, uint32_t &r2, uint32_t &r3,
                                     uint32_t addr) {
    asm volatile("ldmatrix.sync.aligned.m8n8.x4.shared.b16 {%0,%1,%2,%3}, [%4];\n"
                 : "=r"(r0), "=r"(r1), "=r"(r2), "=r"(r3) : "r"(addr));
}

__device__ __forceinline__ void mma_bf16(float *c, const uint32_t *a, const uint32_t *b) {
    asm volatile("mma.sync.aligned.m16n8k16.row.col.f32.bf16.bf16.f32 "
                 "{%0,%1,%2,%3}, {%4,%5,%6,%7}, {%8,%9}, {%0,%1,%2,%3};\n"
                 : "+f"(c[0]), "+f"(c[1]), "+f"(c[2]), "+f"(c[3])
                 : "r"(a[0]), "r"(a[1]), "r"(a[2]), "r"(a[3]), "r"(b[0]), "r"(b[1]));
}

__device__ __forceinline__ float ex2(float x) {
    float y;
    asm("ex2.approx.f32 %0, %1;" : "=f"(y) : "f"(x));
    return y;
}

// ---------------- prep: inputs->bf16 (blocks 0..63) + target dots (blocks 64..95) ----
__global__ void prep_kernel(const float *__restrict__ inputs,
                            const float *__restrict__ cf,
                            const int *__restrict__ indexes,
                            const int *__restrict__ labels) {
    if (blockIdx.x < 64) {
        int i = blockIdx.x * 256 + threadIdx.x;   // 16384 float4s
        const float S = TEMP_INV * LOG2E;
        float4 v = reinterpret_cast<const float4 *>(inputs)[i];
        __nv_bfloat162 lo = __floats2bfloat162_rn(v.x * S, v.y * S);
        __nv_bfloat162 hi = __floats2bfloat162_rn(v.z * S, v.w * S);
        uint2 u;
        u.x = *reinterpret_cast<uint32_t *>(&lo);
        u.y = *reinterpret_cast<uint32_t *>(&hi);
        reinterpret_cast<uint2 *>(g_A)[i] = u;
    } else {
        int lane = threadIdx.x & 31;
        int w = ((blockIdx.x - 64) * 256 + threadIdx.x) >> 5;   // 0..255
        if (w >= B_DIM) return;
        int t = labels[indexes[w]];
        const float4 *a = reinterpret_cast<const float4 *>(inputs + (size_t)w * D_DIM);
        const float4 *b = reinterpret_cast<const float4 *>(cf + (size_t)t * D_DIM);
        float s = 0.f;
#pragma unroll
        for (int i = 0; i < 2; i++) {
            float4 x = a[lane + i * 32];
            float4 y = b[lane + i * 32];
            s += x.x * y.x + x.y * y.y + x.z * y.z + x.w * y.w;
        }
#pragma unroll
        for (int o = 16; o; o >>= 1) s += __shfl_xor_sync(0xffffffffu, s, o);
        if (lane == 0) g_tdot[w] = s * TEMP_INV;
    }
}

// ---------------- producer: batched load, then convert+store ----------------
// Phase 1: all 16 LDG.128 issued back-to-back (MLP=16, ~64KB outstanding/SM).
// Phase 2: CVT + STS. Staging = 64 regs, producer-path only.
static __device__ __forceinline__ void fill_B(const float4 *__restrict__ cfv, int tile,
                                              __nv_bfloat16 *dB, int ptid) {
    const size_t rowbase = (size_t)tile * NTILE;
    float4 v[16];
#pragma unroll
    for (int it = 0; it < 16; it++) {
        int c = ptid + it * 256;       // 0..4095 float4 chunks
        int r = c >> 6;                // 0..63 (N row in tile)
        int kq = c & 63;               // 0..63 (K quad)
        v[it] = cfv[(rowbase + r) * (D_DIM / 4) + kq];
    }
#pragma unroll
    for (int it = 0; it < 16; it++) {
        int c = ptid + it * 256;
        int r = c >> 6;
        int kq = c & 63;
        __nv_bfloat162 lo = __floats2bfloat162_rn(v[it].x, v[it].y);
        __nv_bfloat162 hi = __floats2bfloat162_rn(v[it].z, v[it].w);
        uint2 u;
        u.x = *reinterpret_cast<uint32_t *>(&lo);
        u.y = *reinterpret_cast<uint32_t *>(&hi);
        *reinterpret_cast<uint2 *>(dB + r * LDB + kq * 4) = u;
    }
}

// ---------------- fused GEMM + exp + rowsum + last-CTA finalize ----------------
__global__ void __launch_bounds__(512, 1) gemm_kernel(const float *__restrict__ cf,
                                                      float *__restrict__ out, int G) {
    extern __shared__ char smem[];
    __nv_bfloat16 *sA = reinterpret_cast<__nv_bfloat16 *>(smem);                 // 256*264
    __nv_bfloat16 *sB = reinterpret_cast<__nv_bfloat16 *>(smem + B_DIM * LDA * 2);
    float *sp = reinterpret_cast<float *>(smem + B_DIM * LDA * 2 + 2 * NTILE * LDB * 2);
    __shared__ int s_last;

    const int tid = threadIdx.x;
    const int lane = tid & 31;
    const int warp = tid >> 5;
    const bool producer = (warp >= 8);
    const int bid = blockIdx.x;
    const float4 *cfv = reinterpret_cast<const float4 *>(cf);

    const uint32_t sA32 = (uint32_t)__cvta_generic_to_shared(sA);
    const uint32_t sB32 = (uint32_t)__cvta_generic_to_shared(sB);
    const uint32_t BUFB = NTILE * LDB * 2;

    const int warpM = warp & 3;
    const int warpN = (warp >> 2) & 1;
    const int sub = lane >> 3, r8 = lane & 7;
    const uint32_t aBase =
        sA32 + (uint32_t)(((warpM * 64 + (sub & 1) * 8 + r8) * LDA + (sub >> 1) * 8) * 2);
    const uint32_t bBase0 =
        sB32 + (uint32_t)(((warpN * 32 + (sub >> 1) * 8 + r8) * LDB + (sub & 1) * 8) * 2);

    if (producer) {
        const int ptid = tid - 256;
        // prime buffer 0
        fill_B(cfv, bid, sB, ptid);
        BAR_ARRIVE(1);                           // ready[0]
        int i = 1;
        for (int tile = bid + G; tile < NTILES; tile += G, i++) {
            int b = i & 1;
            if (i >= 2) BAR_SYNC(3 + b);         // wait done[b] from fill i-2
            fill_B(cfv, tile, sB + b * (NTILE * LDB), ptid);
            BAR_ARRIVE(1 + b);                   // ready[b]
        }
    } else {
        // load A (pre-scaled bf16) into padded smem
#pragma unroll
        for (int i = 0; i < 32; i++) {
            int idx = tid + i * 256;
            int row = idx >> 5;
            int col = (idx & 31) << 3;
            *reinterpret_cast<uint4 *>(sA + row * LDA + col) =
                reinterpret_cast<const uint4 *>(g_A)[idx];
        }
        BAR_SYNC_C(5);              // consumers-only: A visible

        float rsum[4][2];
#pragma unroll
        for (int mt = 0; mt < 4; mt++) { rsum[mt][0] = 0.f; rsum[mt][1] = 0.f; }

        int i = 0;
        for (int tile = bid; tile < NTILES; tile += G, i++) {
            int b = i & 1;
            BAR_SYNC(1 + b);        // wait ready[b]

            float acc[4][4][4];
#pragma unroll
            for (int mt = 0; mt < 4; mt++)
#pragma unroll
                for (int nt = 0; nt < 4; nt++)
#pragma unroll
                    for (int q = 0; q < 4; q++) acc[mt][nt][q] = 0.f;

            const uint32_t bBase = bBase0 + b * BUFB;
#pragma unroll
            for (int ks = 0; ks < 16; ks++) {
                uint32_t a[4][4], bb[4][2];
#pragma unroll
                for (int mt = 0; mt < 4; mt++)
                    ldm4(a[mt][0], a[mt][1], a[mt][2], a[mt][3],
                         aBase + (uint32_t)(mt * 16 * LDA * 2 + ks * 32));
                {
                    uint32_t q0, q1, q2, q3;
                    ldm4(q0, q1, q2, q3, bBase + (uint32_t)(ks * 32));
                    bb[0][0] = q0; bb[0][1] = q1; bb[1][0] = q2; bb[1][1] = q3;
                    ldm4(q0, q1, q2, q3, bBase + (uint32_t)(16 * LDB * 2 + ks * 32));
                    bb[2][0] = q0; bb[2][1] = q1; bb[3][0] = q2; bb[3][1] = q3;
                }
#pragma unroll
                for (int mt = 0; mt < 4; mt++)
#pragma unroll
                    for (int nt = 0; nt < 4; nt++)
                        mma_bf16(acc[mt][nt], a[mt], bb[nt]);
            }
            BAR_ARRIVE(3 + b);      // done[b] (epilogue off handoff path)

            // epilogue: acc holds logits*log2e -> ex2 + rowsum
#pragma unroll
            for (int mt = 0; mt < 4; mt++) {
                float lo = 0.f, hi = 0.f;
#pragma unroll
                for (int nt = 0; nt < 4; nt++) {
                    lo += ex2(acc[mt][nt][0]) + ex2(acc[mt][nt][1]);
                    hi += ex2(acc[mt][nt][2]) + ex2(acc[mt][nt][3]);
                }
                rsum[mt][0] += lo;
                rsum[mt][1] += hi;
            }
        }

        // reduce across quad, stage per-m sums in sp
#pragma unroll
        for (int mt = 0; mt < 4; mt++)
#pragma unroll
            for (int h = 0; h < 2; h++) {
                float vv = rsum[mt][h];
                vv += __shfl_xor_sync(0xffffffffu, vv, 1);
                vv += __shfl_xor_sync(0xffffffffu, vv, 2);
                if ((lane & 3) == 0)
                    sp[warpN * 256 + warpM * 64 + mt * 16 + h * 8 + (lane >> 2)] = vv;
            }
    }

    __syncthreads();
    if (tid < B_DIM)
        g_partial[tid * GSTRIDE + bid] = sp[tid] + sp[256 + tid];
    __threadfence();
    __syncthreads();
    if (tid == 0) {
        int old = atomicAdd(&g_done, 1);
        s_last = (old == G - 1) ? 1 : 0;
    }
    __syncthreads();

    if (s_last) {
        // final reduction (L2-hot partials)
        float vv = 0.f;
        if (tid < B_DIM) {
            const float4 *row = reinterpret_cast<const float4 *>(g_partial + tid * GSTRIDE);
            float s0 = 0.f, s1 = 0.f, s2 = 0.f, s3 = 0.f;
            int g4 = G >> 2;
#pragma unroll 4
            for (int i = 0; i < g4; i++) {
                float4 v = row[i];
                s0 += v.x; s1 += v.y; s2 += v.z; s3 += v.w;
            }
            float S = (s0 + s1) + (s2 + s3);
            for (int g = g4 << 2; g < G; g++) S += g_partial[tid * GSTRIDE + g];
            float lt = g_tdot[tid];
            vv = logf(expf(lt) / (S + EPS_SM) + EPS_LOG);
        }
        __syncthreads();   // sp reuse safe
        if (tid < B_DIM) sp[tid] = vv;
        __syncthreads();
#pragma unroll
        for (int s = 128; s > 0; s >>= 1) {
            if (tid < s) sp[tid] += sp[tid + s];
            __syncthreads();
        }
        if (tid == 0) {
            out[0] = -sp[0] / (float)B_DIM;
            g_done = 0;   // reset for next graph replay
        }
    }
}

// ---------------- launch ----------------
extern "C" void kernel_launch(void *const *d_in, const int *in_sizes, int n_in,
                              void *d_out, int out_size) {
    const float *inputs = (const float *)d_in[0];
    const float *cf     = (const float *)d_in[1];
    // d_in[2] instance_features: unused by the reference loss
    const int *indexes  = (const int *)d_in[3];
    const int *labels   = (const int *)d_in[4];
    float *out          = (float *)d_out;

    int dev = 0;
    cudaGetDevice(&dev);
    int sm = 148;
    cudaDeviceGetAttribute(&sm, cudaDevAttrMultiProcessorCount, dev);
    int G = sm;
    if (G < 1) G = 148;
    if (G > GSTRIDE) G = GSTRIDE;
    if (G > NTILES) G = NTILES;

    const int smemBytes = B_DIM * LDA * 2 + 2 * NTILE * LDB * 2 + 512 * 4;  // 204800
    cudaFuncSetAttribute(gemm_kernel, cudaFuncAttributeMaxDynamicSharedMemorySize, smemBytes);

    prep_kernel<<<96, 256>>>(inputs, cf, indexes, labels);
    gemm_kernel<<<G, 512, smemBytes>>>(cf, out, G);
}